// round 16
// baseline (speedup 1.0000x reference)
#include <cuda_runtime.h>
#include <math.h>

// ----------------------------------------------------------------------------
// LayerNormLSTM, fp32. B=64, S=48, E=512, H=512, 4H=2048. Output [64,1024].
//   phase-1: transpose + big f32x2 GEMM LN(x @ W_ih0^T) -> g_G0
//   layer0/1: persistent recurrence kernel, 128 blocks x 512 threads,
//             intra-block split-K (two 8-warp halves), grid barriers.
// ----------------------------------------------------------------------------

#define EPSF 1e-5f
#define Bn   64
#define Sn   48
#define En   512
#define Hn   512
#define G4n  2048

// --------------------------- scratch (device globals) ------------------------
__device__ float g_xseq[Sn * Bn * En];
__device__ float g_G0[2 * Sn * Bn * G4n];
__device__ float g_G1[2 * Bn * G4n];
__device__ float g_z [2 * Bn * G4n];
__device__ float g_h [2 * Bn * Hn];
__device__ float g_c [2 * Bn * Hn];
__device__ float g_xc[Bn * 2 * Hn];
__device__ unsigned g_barcnt = 0;
__device__ unsigned g_bargen = 0;

// --------------------------- packed fp32x2 FMA --------------------------------
union F2U { float2 f; unsigned long long u; };
__device__ __forceinline__ float2 ffma2(float2 a, float2 b, float2 c) {
    F2U ua, ub, uc, ud;
    ua.f = a; ub.f = b; uc.f = c;
    asm("fma.rn.f32x2 %0, %1, %2, %3;"
        : "=l"(ud.u) : "l"(ua.u), "l"(ub.u), "l"(uc.u));
    return ud.f;
}

// --------------------------- helpers ----------------------------------------
__device__ __forceinline__ void block_reduce2(float& a, float& b, float* sbuf) {
    int tid = threadIdx.x;
#pragma unroll
    for (int off = 16; off > 0; off >>= 1) {
        a += __shfl_down_sync(0xffffffffu, a, off);
        b += __shfl_down_sync(0xffffffffu, b, off);
    }
    int warp = tid >> 5, lane = tid & 31, nw = blockDim.x >> 5;
    if (lane == 0) { sbuf[warp] = a; sbuf[32 + warp] = b; }
    __syncthreads();
    if (warp == 0) {
        a = (lane < nw) ? sbuf[lane] : 0.f;
        b = (lane < nw) ? sbuf[32 + lane] : 0.f;
#pragma unroll
        for (int off = 16; off > 0; off >>= 1) {
            a += __shfl_down_sync(0xffffffffu, a, off);
            b += __shfl_down_sync(0xffffffffu, b, off);
        }
        if (lane == 0) { sbuf[0] = a; sbuf[32] = b; }
    }
    __syncthreads();
    a = sbuf[0];
    b = sbuf[32];
    __syncthreads();
}

// Grid-wide barrier. All 128 blocks co-resident (128 <= 148 SMs).
__device__ __forceinline__ void grid_bar(unsigned nb) {
    __syncthreads();
    if (threadIdx.x == 0) {
        unsigned gen = *(volatile unsigned*)&g_bargen;
        __threadfence();
        unsigned t = atomicAdd(&g_barcnt, 1u);
        if (t == nb - 1u) {
            atomicExch(&g_barcnt, 0u);
            __threadfence();
            atomicAdd(&g_bargen, 1u);
        } else {
            while (*(volatile unsigned*)&g_bargen == gen) { __nanosleep(64); }
        }
        __threadfence();
    }
    __syncthreads();
}

// --------------------------- scalar SGEMM (small, ih1 only) -------------------
template <int BM, int BN, int BK, int TM, int TN>
__device__ __forceinline__ void sgemm_nt_body(
    const float* __restrict__ Ad, const float* __restrict__ Bd,
    float* __restrict__ Cd, int M, int N, int K) {
    constexpr int THREADS = (BM / TM) * (BN / TN);
    __shared__ float As[BK][BM];
    __shared__ float Bs[BK][BN];
    const int m0 = blockIdx.y * BM;
    const int n0 = blockIdx.x * BN;
    const int tid = threadIdx.x;
    const int tm = (tid / (BN / TN)) * TM;
    const int tn = (tid % (BN / TN)) * TN;
    float acc[TM][TN];
#pragma unroll
    for (int i = 0; i < TM; i++)
#pragma unroll
        for (int j = 0; j < TN; j++) acc[i][j] = 0.f;
    for (int k0 = 0; k0 < K; k0 += BK) {
        constexpr int AV = BM * BK / 4;
        constexpr int KQ = BK / 4;
#pragma unroll
        for (int v = tid; v < AV; v += THREADS) {
            int row = v / KQ, kq = (v % KQ) * 4;
            float4 t = *(const float4*)(Ad + (size_t)(m0 + row) * K + k0 + kq);
            As[kq + 0][row] = t.x; As[kq + 1][row] = t.y;
            As[kq + 2][row] = t.z; As[kq + 3][row] = t.w;
        }
        constexpr int BV = BN * BK / 4;
#pragma unroll
        for (int v = tid; v < BV; v += THREADS) {
            int row = v / KQ, kq = (v % KQ) * 4;
            float4 t = *(const float4*)(Bd + (size_t)(n0 + row) * K + k0 + kq);
            Bs[kq + 0][row] = t.x; Bs[kq + 1][row] = t.y;
            Bs[kq + 2][row] = t.z; Bs[kq + 3][row] = t.w;
        }
        __syncthreads();
#pragma unroll
        for (int kk = 0; kk < BK; kk++) {
            float a[TM], bfr[TN];
#pragma unroll
            for (int i = 0; i < TM; i++) a[i] = As[kk][tm + i];
#pragma unroll
            for (int j = 0; j < TN; j++) bfr[j] = Bs[kk][tn + j];
#pragma unroll
            for (int i = 0; i < TM; i++)
#pragma unroll
                for (int j = 0; j < TN; j++)
                    acc[i][j] = fmaf(a[i], bfr[j], acc[i][j]);
        }
        __syncthreads();
    }
#pragma unroll
    for (int i = 0; i < TM; i++)
#pragma unroll
        for (int j = 0; j < TN; j++)
            Cd[(size_t)(m0 + tm + i) * N + n0 + tn + j] = acc[i][j];
}

// --------------------------- kernels ----------------------------------------

// x[B,S,E] -> g_xseq[S,B,E]
__global__ void k_transpose(const float* __restrict__ x) {
    int sb = blockIdx.x;
    int s = sb / Bn, b = sb % Bn;
    const float4* src = (const float4*)(x + ((size_t)b * Sn + s) * En);
    float4* dst = (float4*)(g_xseq + (size_t)sb * En);
    dst[threadIdx.x] = src[threadIdx.x];
}

// Phase-1 big GEMM with packed f32x2 FMA.
__global__ void __launch_bounds__(256)
k_gemm_ih0(const float* __restrict__ w) {
    __shared__ float2 As2[16][129];
    __shared__ float  Bs[16][132];
    const int d = blockIdx.z;
    const float* Ad = g_xseq;
    const float* Bd = w + (size_t)d * G4n * En;
    float* Cd = g_G0 + (size_t)d * (Sn * Bn) * G4n;
    const int m0 = blockIdx.y * 128, n0 = blockIdx.x * 128;
    const int tid = threadIdx.x;
    const int mg = tid >> 4, ng = tid & 15;

    float2 acc[8][4];
#pragma unroll
    for (int i = 0; i < 8; i++)
#pragma unroll
        for (int j = 0; j < 4; j++) acc[i][j] = make_float2(0.f, 0.f);

    float4 av[2], bv[2];
    {
#pragma unroll
        for (int t = 0; t < 2; t++) {
            int v = tid + 256 * t;
            int m = v >> 2, kk = (v & 3) * 4;
            av[t] = *(const float4*)(Ad + (size_t)(m0 + m) * En + kk);
            bv[t] = *(const float4*)(Bd + (size_t)(n0 + m) * En + kk);
        }
    }
    for (int kc = 0; kc < 32; kc++) {
#pragma unroll
        for (int t = 0; t < 2; t++) {
            int v = tid + 256 * t;
            int m = v >> 2, kk = (v & 3) * 4;
            As2[kk + 0][m] = make_float2(av[t].x, av[t].x);
            As2[kk + 1][m] = make_float2(av[t].y, av[t].y);
            As2[kk + 2][m] = make_float2(av[t].z, av[t].z);
            As2[kk + 3][m] = make_float2(av[t].w, av[t].w);
            Bs[kk + 0][m] = bv[t].x;
            Bs[kk + 1][m] = bv[t].y;
            Bs[kk + 2][m] = bv[t].z;
            Bs[kk + 3][m] = bv[t].w;
        }
        __syncthreads();
        if (kc < 31) {
            int k0 = (kc + 1) * 16;
#pragma unroll
            for (int t = 0; t < 2; t++) {
                int v = tid + 256 * t;
                int m = v >> 2, kk = (v & 3) * 4;
                av[t] = *(const float4*)(Ad + (size_t)(m0 + m) * En + k0 + kk);
                bv[t] = *(const float4*)(Bd + (size_t)(n0 + m) * En + k0 + kk);
            }
        }
#pragma unroll
        for (int kk = 0; kk < 16; kk++) {
            float2 a[8], wv[4];
#pragma unroll
            for (int i = 0; i < 8; i++) a[i] = As2[kk][mg + 16 * i];
#pragma unroll
            for (int j = 0; j < 4; j++)
                wv[j] = *(const float2*)&Bs[kk][2 * ng + 32 * j];
#pragma unroll
            for (int i = 0; i < 8; i++)
#pragma unroll
                for (int j = 0; j < 4; j++)
                    acc[i][j] = ffma2(a[i], wv[j], acc[i][j]);
        }
        __syncthreads();
    }
#pragma unroll
    for (int i = 0; i < 8; i++)
#pragma unroll
        for (int j = 0; j < 4; j++)
            *(float2*)(Cd + (size_t)(m0 + mg + 16 * i) * G4n + n0 + 2 * ng + 32 * j)
                = acc[i][j];
}

// layer-1 input GEMM (once): g_z[d] = g_xc @ w_ih1[d]^T
__global__ void __launch_bounds__(256)
k_gemm_ih1(const float* __restrict__ w_ih1) {
    const int d = blockIdx.z;
    sgemm_nt_body<64, 32, 16, 4, 2>(
        g_xc, w_ih1 + (size_t)d * G4n * (2 * Hn),
        g_z + (size_t)d * Bn * G4n, Bn, G4n, 2 * Hn);
}

// Row-wise LayerNorm over rows of length 2048.
__global__ void __launch_bounds__(256)
k_ln_rows(int which, const float* __restrict__ gamma,
          const float* __restrict__ beta, int rows_per_dir) {
    __shared__ float sbuf[64];
    int row = blockIdx.x;
    int d = row / rows_per_dir;
    const float* src = (which == 0 ? g_G0 : g_z) + (size_t)row * G4n;
    float* dst = (which == 0 ? g_G0 : g_G1) + (size_t)row * G4n;
    const float* ga = gamma + (size_t)d * G4n;
    const float* be = beta + (size_t)d * G4n;
    int tid = threadIdx.x;
    float v[8];
    float s = 0.f, s2 = 0.f;
#pragma unroll
    for (int i = 0; i < 8; i++) {
        v[i] = src[tid + i * 256];
        s += v[i];
        s2 += v[i] * v[i];
    }
    block_reduce2(s, s2, sbuf);
    float mu = s * (1.f / G4n);
    float var = s2 * (1.f / G4n) - mu * mu;
    var = var < 0.f ? 0.f : var;
    float r = rsqrtf(var + EPSF);
#pragma unroll
    for (int i = 0; i < 8; i++) {
        int idx = tid + i * 256;
        dst[idx] = (v[i] - mu) * r * ga[idx] + be[idx];
    }
}

// --------------------------- persistent recurrence ---------------------------
// 128 blocks x 512 threads. All 48 steps of one layer (both dirs).
// Phase G: block (d,q) computes z[d, all b, q*32..q*32+31] = h @ W^T slice,
//          split-K: warps 0-7 do K[0:256), warps 8-15 do K[256:512),
//          partials combined through smem.
// Phase S: block (d,q=b) does the fused LN/LSTM cell update (1 cell/thread).
__global__ void __launch_bounds__(512)
k_recur(int layer0, const float* __restrict__ W,
        const float* __restrict__ ln_hh_g, const float* __restrict__ ln_hh_b,
        const float* __restrict__ ln_ho_g, const float* __restrict__ ln_ho_b) {
    __shared__ float2 As2[2][32][66];   // duplicated h {h,h}: [half][kk][b]
    __shared__ float  Bs[2][32][36];    // W slice: [half][kk][n]
    __shared__ float  comb[256 * 8];    // half-1 partial accumulators
    __shared__ float  sbuf[64];

    const int r = blockIdx.x;        // 0..127
    const int tid = threadIdx.x;     // 0..511
    const int d = r >> 6, q = r & 63;
    const int half = tid >> 8;       // 0/1 (K-split)
    const int ht = tid & 255;

    // init h = c = 0 for this block's (d,q) row (one element per thread)
    g_h[(size_t)(d * Bn + q) * Hn + tid] = 0.f;
    g_c[(size_t)(d * Bn + q) * Hn + tid] = 0.f;
    __threadfence();
    grid_bar(128);

    // K-half base pointers
    const float* Wh = W + ((size_t)d * G4n + (size_t)(q * 32)) * Hn + half * 256;
    const float* hsrc = g_h + (size_t)d * Bn * Hn + half * 256;  // row stride Hn
    const int bg = ht >> 3;        // 0..31 -> b = bg, bg+32
    const int ng = ht & 7;         // n pairs at 2ng, 2ng+16

    const float* GA = ln_hh_g + (size_t)d * G4n;
    const float* BA = ln_hh_b + (size_t)d * G4n;
    const float* GO = ln_ho_g + (size_t)d * Hn;
    const float* BO = ln_ho_b + (size_t)d * Hn;

    for (int step = 0; step < Sn; step++) {
        // ================= phase G: z slice = h @ W^T (split-K) ==========
        {
            float2 acc[2][2];
#pragma unroll
            for (int i = 0; i < 2; i++)
#pragma unroll
                for (int j = 0; j < 2; j++) acc[i][j] = make_float2(0.f, 0.f);

            float4 hv[2], wv;
            // preload chunk 0 of this K-half
            {
#pragma unroll
                for (int t = 0; t < 2; t++) {
                    int v = ht + 256 * t;        // 0..511
                    int b = v >> 3, kk = (v & 7) * 4;
                    hv[t] = __ldcg((const float4*)(hsrc + (size_t)b * Hn + kk));
                }
                int n = ht >> 3, kk = (ht & 7) * 4;
                wv = *(const float4*)(Wh + (size_t)n * Hn + kk);
            }
            for (int kc = 0; kc < 8; kc++) {     // 8 chunks x 32 kk = 256 K
#pragma unroll
                for (int t = 0; t < 2; t++) {
                    int v = ht + 256 * t;
                    int b = v >> 3, kk = (v & 7) * 4;
                    As2[half][kk + 0][b] = make_float2(hv[t].x, hv[t].x);
                    As2[half][kk + 1][b] = make_float2(hv[t].y, hv[t].y);
                    As2[half][kk + 2][b] = make_float2(hv[t].z, hv[t].z);
                    As2[half][kk + 3][b] = make_float2(hv[t].w, hv[t].w);
                }
                {
                    int n = ht >> 3, kk = (ht & 7) * 4;
                    Bs[half][kk + 0][n] = wv.x;
                    Bs[half][kk + 1][n] = wv.y;
                    Bs[half][kk + 2][n] = wv.z;
                    Bs[half][kk + 3][n] = wv.w;
                }
                __syncthreads();
                if (kc < 7) {
                    int k0 = (kc + 1) * 32;
#pragma unroll
                    for (int t = 0; t < 2; t++) {
                        int v = ht + 256 * t;
                        int b = v >> 3, kk = (v & 7) * 4;
                        hv[t] = __ldcg((const float4*)(hsrc + (size_t)b * Hn + k0 + kk));
                    }
                    int n = ht >> 3, kk = (ht & 7) * 4;
                    wv = *(const float4*)(Wh + (size_t)n * Hn + k0 + kk);
                }
#pragma unroll
                for (int kk = 0; kk < 32; kk++) {
                    float2 a0 = As2[half][kk][bg];
                    float2 a1 = As2[half][kk][bg + 32];
                    float2 w0 = *(const float2*)&Bs[half][kk][2 * ng];
                    float2 w1 = *(const float2*)&Bs[half][kk][2 * ng + 16];
                    acc[0][0] = ffma2(a0, w0, acc[0][0]);
                    acc[0][1] = ffma2(a0, w1, acc[0][1]);
                    acc[1][0] = ffma2(a1, w0, acc[1][0]);
                    acc[1][1] = ffma2(a1, w1, acc[1][1]);
                }
                __syncthreads();
            }
            // combine the two K-halves: half 1 -> smem, half 0 adds + stores
            if (half == 1) {
                float* cb = comb + ht * 8;
                cb[0] = acc[0][0].x; cb[1] = acc[0][0].y;
                cb[2] = acc[0][1].x; cb[3] = acc[0][1].y;
                cb[4] = acc[1][0].x; cb[5] = acc[1][0].y;
                cb[6] = acc[1][1].x; cb[7] = acc[1][1].y;
            }
            __syncthreads();
            if (half == 0) {
                const float* cb = comb + ht * 8;
                acc[0][0].x += cb[0]; acc[0][0].y += cb[1];
                acc[0][1].x += cb[2]; acc[0][1].y += cb[3];
                acc[1][0].x += cb[4]; acc[1][0].y += cb[5];
                acc[1][1].x += cb[6]; acc[1][1].y += cb[7];
#pragma unroll
                for (int i = 0; i < 2; i++) {
                    int b = bg + 32 * i;
                    float* zrow = g_z + (size_t)(d * Bn + b) * G4n + q * 32;
                    *(float2*)(zrow + 2 * ng) = acc[i][0];
                    *(float2*)(zrow + 2 * ng + 16) = acc[i][1];
                }
            }
        }
        __threadfence();
        grid_bar(128);

        // ================= phase S: fused LN/LSTM cell (1 cell/thread) ====
        {
            const float* zrow = g_z + (size_t)(d * Bn + q) * G4n;
            const float* gih;
            if (layer0) {
                int t = (d == 0) ? step : (Sn - 1 - step);
                gih = g_G0 + (((size_t)d * Sn + t) * Bn + q) * G4n;
            } else {
                gih = g_G1 + ((size_t)d * Bn + q) * G4n;
            }

            float zv[4];
            float s = 0.f, s2 = 0.f;
#pragma unroll
            for (int i = 0; i < 4; i++) {
                zv[i] = __ldcg(zrow + tid + i * 512);
                s += zv[i];
                s2 += zv[i] * zv[i];
            }
            block_reduce2(s, s2, sbuf);
            float mu = s * (1.f / G4n);
            float var = s2 * (1.f / G4n) - mu * mu;
            var = var < 0.f ? 0.f : var;
            float rinv = rsqrtf(var + EPSF);

            float g0 = gih[tid]        + (zv[0] - mu) * rinv * GA[tid]        + BA[tid];
            float g1 = gih[tid + 512]  + (zv[1] - mu) * rinv * GA[tid + 512]  + BA[tid + 512];
            float g2 = gih[tid + 1024] + (zv[2] - mu) * rinv * GA[tid + 1024] + BA[tid + 1024];
            float g3 = gih[tid + 1536] + (zv[3] - mu) * rinv * GA[tid + 1536] + BA[tid + 1536];
            float ig = 1.f / (1.f + expf(-g0));
            float fg = 1.f / (1.f + expf(-g1));
            float og = 1.f / (1.f + expf(-g2));
            float gg = tanhf(g3);

            size_t cidx = (size_t)(d * Bn + q) * Hn + tid;
            float c = fg * g_c[cidx] + ig * gg;   // c is block-private: plain ld
            g_c[cidx] = c;

            float cs = c, cs2 = c * c;
            block_reduce2(cs, cs2, sbuf);
            float muc = cs * (1.f / Hn);
            float varc = cs2 * (1.f / Hn) - muc * muc;
            varc = varc < 0.f ? 0.f : varc;
            float rc = rsqrtf(varc + EPSF);

            float hn = og * tanhf((c - muc) * rc * GO[tid] + BO[tid]);
            g_h[(size_t)(d * Bn + q) * Hn + tid] = hn;
        }
        __threadfence();
        grid_bar(128);
    }
}

// xc[b] = concat(h_fwd[b], h_bwd[b])
__global__ void k_build_xc() {
    int b = blockIdx.x, t = threadIdx.x;
    g_xc[(size_t)b * 1024 + t]       = g_h[(size_t)(0 * Bn + b) * Hn + t];
    g_xc[(size_t)b * 1024 + 512 + t] = g_h[(size_t)(1 * Bn + b) * Hn + t];
}

__global__ void k_out(float* __restrict__ out) {
    int b = blockIdx.x, t = threadIdx.x;
    out[(size_t)b * 1024 + t]       = g_h[(size_t)(0 * Bn + b) * Hn + t];
    out[(size_t)b * 1024 + 512 + t] = g_h[(size_t)(1 * Bn + b) * Hn + t];
}

// --------------------------- launch -----------------------------------------
extern "C" void kernel_launch(void* const* d_in, const int* in_sizes, int n_in,
                              void* d_out, int out_size) {
    (void)in_sizes; (void)n_in; (void)out_size;

    const float* x        = (const float*)d_in[0];
    const float* w_ih0    = (const float*)d_in[2];
    const float* w_hh0    = (const float*)d_in[3];
    const float* ln_ih0_g = (const float*)d_in[4];
    const float* ln_ih0_b = (const float*)d_in[5];
    const float* ln_hh0_g = (const float*)d_in[6];
    const float* ln_hh0_b = (const float*)d_in[7];
    const float* ln_ho0_g = (const float*)d_in[8];
    const float* ln_ho0_b = (const float*)d_in[9];
    const float* w_ih1    = (const float*)d_in[10];
    const float* w_hh1    = (const float*)d_in[11];
    const float* ln_ih1_g = (const float*)d_in[12];
    const float* ln_ih1_b = (const float*)d_in[13];
    const float* ln_hh1_g = (const float*)d_in[14];
    const float* ln_hh1_b = (const float*)d_in[15];
    const float* ln_ho1_g = (const float*)d_in[16];
    const float* ln_ho1_b = (const float*)d_in[17];
    float* out = (float*)d_out;

    // ---- phase 1 ----
    k_transpose<<<Sn * Bn, 128>>>(x);
    k_gemm_ih0<<<dim3(G4n / 128, (Sn * Bn) / 128, 2), 256>>>(w_ih0);
    k_ln_rows<<<2 * Sn * Bn, 256>>>(0, ln_ih0_g, ln_ih0_b, Sn * Bn);

    // ---- layer 0: persistent recurrence ----
    k_recur<<<128, 512>>>(1, w_hh0, ln_hh0_g, ln_hh0_b, ln_ho0_g, ln_ho0_b);

    // ---- layer 1 constant input ----
    k_build_xc<<<Bn, 512>>>();
    k_gemm_ih1<<<dim3(G4n / 32, 1, 2), 256>>>(w_ih1);
    k_ln_rows<<<2 * Bn, 256>>>(1, ln_ih1_g, ln_ih1_b, Bn);

    // ---- layer 1: persistent recurrence ----
    k_recur<<<128, 512>>>(0, w_hh1, ln_hh1_g, ln_hh1_b, ln_ho1_g, ln_ho1_b);

    // ---- output ----
    k_out<<<Bn, 512>>>(out);
}